// round 3
// baseline (speedup 1.0000x reference)
#include <cuda_runtime.h>
#include <math.h>
#include <stdint.h>

// Problem constants: B=8, L=1024, D=1024, F=4096, nh=8, hs=128, M=B*L=8192
#define BM 128
#define BN 128
#define BKt 16

// Scratch (static device globals; no runtime allocation)
__device__ float g_ln[8388608];        // 8192*1024   LN output
__device__ float g_qkv[25165824];      // 8192*3072   QKV
__device__ float g_scores[67108864];   // 64*1024*1024  S then P
__device__ float g_qer[67108864];      // 64*1024*1024  QEr
__device__ float g_y[8388608];         // 8192*1024   attention output
__device__ float g_h[33554432];        // 8192*4096   MLP hidden

__device__ __forceinline__ uint32_t f2tf(float x) {
    uint32_t u;
    asm("cvt.rna.tf32.f32 %0, %1;" : "=r"(u) : "f"(x));
    return u;
}

__device__ __forceinline__ void mma_tf32(float c[4],
    uint32_t a0, uint32_t a1, uint32_t a2, uint32_t a3,
    uint32_t b0, uint32_t b1)
{
    asm volatile(
        "mma.sync.aligned.m16n8k8.row.col.f32.tf32.tf32.f32 "
        "{%0,%1,%2,%3}, {%4,%5,%6,%7}, {%8,%9}, {%0,%1,%2,%3};"
        : "+f"(c[0]), "+f"(c[1]), "+f"(c[2]), "+f"(c[3])
        : "r"(a0), "r"(a1), "r"(a2), "r"(a3), "r"(b0), "r"(b1));
}

// ---------------------------------------------------------------------------
// tf32 tensor-core GEMM: C = A(MxK) * op(B) (+bias)(+gelu/+residual)
// Fragment-major shared memory:
//   Af[k8:2][m16:8][slot:32][reg:4]  (u32)  — LDS.128 per lane per m-tile
//     slot(g,tg) = ((g + 2*tg)&7) + 8*tg ;  reg = hi + 2*khi
//   Bf[krow:8][n:128 pairs] u64, row stride 264 u32 — LDS.64 per lane per n-tile
//     krow = k8*4 + t holds pair (B[k8*8+t][n], B[k8*8+t+4][n])
// epilogue: 0=none, 1=+bias, 2=+bias+GELU, 3=+bias+residual
// tri: 0=full, 1=lower-tri tile skip, 2=anti-tri tile skip, 3=causal K bound
// ---------------------------------------------------------------------------
template <bool TRANSB>
__global__ void __launch_bounds__(256, 2)
gemm_tf32(const float* __restrict__ A, int lda, long long sAhi, long long sAlo,
          const float* __restrict__ Bm, int ldb, long long sBhi, long long sBlo,
          float* __restrict__ C, int ldc, long long sChi, long long sClo,
          int N, int K,
          const float* __restrict__ bias, const float* __restrict__ resid,
          int epilogue, int tri)
{
    const int n0 = blockIdx.x * BN;
    const int m0 = blockIdx.y * BM;
    if (tri == 1 && n0 > m0) return;
    if (tri == 2 && (m0 + n0) < (N - BM - BN + 1)) return;
    const int kmax = (tri == 3) ? min(K, m0 + BM) : K;

    const int z = blockIdx.z, hi = z >> 3, lo = z & 7;
    A  += hi * sAhi + lo * sAlo;
    Bm += hi * sBhi + lo * sBlo;
    const long long coff = hi * sChi + lo * sClo;

    __shared__ __align__(16) uint32_t Af[2048];  // 2*8*32*4
    __shared__ __align__(16) uint32_t Bf[2112];  // 8*264

    const int tid  = threadIdx.x;
    const int lane = tid & 31;
    const int warp = tid >> 5;
    const int g  = lane >> 2;   // 0..7
    const int tg = lane & 3;    // 0..3
    const int wm16 = (warp >> 2) * 4;   // m16 base (rows wm16*16)
    const int wn   = (warp & 3) * 32;
    const int aslot = ((g + 2 * tg) & 7) + 8 * tg;

    // ---- A staging indices: thread handles row ra, k-half k8s ----
    const int ra  = tid >> 1;
    const int k8s = tid & 1;
    const int rr  = ra & 15;
    const int gs  = rr & 7;
    const int his = (rr >> 3) & 1;
    const int abase = (((k8s << 3) + (ra >> 4)) << 7) + his;  // *128
    int sE0 = ((gs + 0) & 7) + 0;
    int sE1 = ((gs + 2) & 7) + 8;
    int sE2 = ((gs + 4) & 7) + 16;
    int sE3 = ((gs + 6) & 7) + 24;
    const float* Ap = A + (size_t)(m0 + ra) * lda + k8s * 8;

    // ---- B staging indices ----
    int bbase;
    const float* Bp;
    if (TRANSB) {               // B row-major NxK: thread = (n=tid>>1, khalf)
        const int rbn = tid >> 1;
        bbase = (k8s << 2) * 264 + rbn * 2;
        Bp = Bm + (size_t)(n0 + rbn) * ldb + k8s * 8;
    } else {                    // B row-major KxN: thread = (k=tid&15, nhalf)
        const int r  = tid & 15;
        const int nh = tid >> 4;
        bbase = (((r >> 3) << 2) + (r & 3)) * 264 + ((r >> 2) & 1) + nh * 16;
        Bp = Bm + (size_t)r * ldb + n0 + nh * 8;
    }

    float4 aR0, aR1, bR0, bR1;
    float acc[4][4][4] = {};

#define STAGE_A() do { \
        Af[abase + sE0 * 4    ] = f2tf(aR0.x); \
        Af[abase + sE1 * 4    ] = f2tf(aR0.y); \
        Af[abase + sE2 * 4    ] = f2tf(aR0.z); \
        Af[abase + sE3 * 4    ] = f2tf(aR0.w); \
        Af[abase + sE0 * 4 + 2] = f2tf(aR1.x); \
        Af[abase + sE1 * 4 + 2] = f2tf(aR1.y); \
        Af[abase + sE2 * 4 + 2] = f2tf(aR1.z); \
        Af[abase + sE3 * 4 + 2] = f2tf(aR1.w); \
    } while (0)

#define STAGE_B() do { \
        if (TRANSB) { \
            *(uint2*)&Bf[bbase          ] = make_uint2(f2tf(bR0.x), f2tf(bR1.x)); \
            *(uint2*)&Bf[bbase + 264    ] = make_uint2(f2tf(bR0.y), f2tf(bR1.y)); \
            *(uint2*)&Bf[bbase + 2 * 264] = make_uint2(f2tf(bR0.z), f2tf(bR1.z)); \
            *(uint2*)&Bf[bbase + 3 * 264] = make_uint2(f2tf(bR0.w), f2tf(bR1.w)); \
        } else { \
            Bf[bbase     ] = f2tf(bR0.x); \
            Bf[bbase +  2] = f2tf(bR0.y); \
            Bf[bbase +  4] = f2tf(bR0.z); \
            Bf[bbase +  6] = f2tf(bR0.w); \
            Bf[bbase +  8] = f2tf(bR1.x); \
            Bf[bbase + 10] = f2tf(bR1.y); \
            Bf[bbase + 12] = f2tf(bR1.z); \
            Bf[bbase + 14] = f2tf(bR1.w); \
        } \
    } while (0)

    // prologue: tile 0
    aR0 = *(const float4*)(Ap);
    aR1 = *(const float4*)(Ap + 4);
    if (TRANSB) {
        bR0 = *(const float4*)(Bp);
        bR1 = *(const float4*)(Bp + 4);
    } else {
        bR0 = *(const float4*)(Bp);
        bR1 = *(const float4*)(Bp + 4);
    }
    STAGE_A();
    STAGE_B();
    __syncthreads();

    for (int k0 = 0; k0 < kmax; k0 += BKt) {
        const bool nxt = (k0 + BKt) < kmax;
        if (nxt) {
            aR0 = *(const float4*)(Ap + k0 + BKt);
            aR1 = *(const float4*)(Ap + k0 + BKt + 4);
            if (TRANSB) {
                bR0 = *(const float4*)(Bp + k0 + BKt);
                bR1 = *(const float4*)(Bp + k0 + BKt + 4);
            } else {
                bR0 = *(const float4*)(Bp + (size_t)(k0 + BKt) * ldb);
                bR1 = *(const float4*)(Bp + (size_t)(k0 + BKt) * ldb + 4);
            }
        }
#pragma unroll
        for (int k8 = 0; k8 < 2; k8++) {
            uint4 av[4];
            uint2 bv[4];
#pragma unroll
            for (int mt = 0; mt < 4; mt++)
                av[mt] = *(const uint4*)&Af[(((k8 << 3) + wm16 + mt) << 7) + aslot * 4];
#pragma unroll
            for (int nt = 0; nt < 4; nt++)
                bv[nt] = *(const uint2*)&Bf[((k8 << 2) + tg) * 264 + (wn + nt * 8 + g) * 2];
#pragma unroll
            for (int mt = 0; mt < 4; mt++)
#pragma unroll
                for (int nt = 0; nt < 4; nt++)
                    mma_tf32(acc[mt][nt],
                             av[mt].x, av[mt].y, av[mt].z, av[mt].w,
                             bv[nt].x, bv[nt].y);
        }
        __syncthreads();
        if (nxt) {
            STAGE_A();
            STAGE_B();
            __syncthreads();
        }
    }

    // Epilogue (same fragment->C mapping as before)
#pragma unroll
    for (int mt = 0; mt < 4; mt++) {
#pragma unroll
        for (int nt = 0; nt < 4; nt++) {
            const int r  = m0 + (wm16 + mt) * 16 + g;
            const int cb = n0 + wn + nt * 8 + tg * 2;
            float b0 = 0.f, b1 = 0.f;
            if (epilogue) { b0 = bias[cb]; b1 = bias[cb + 1]; }
            float o00 = acc[mt][nt][0] + b0, o01 = acc[mt][nt][1] + b1;
            float o10 = acc[mt][nt][2] + b0, o11 = acc[mt][nt][3] + b1;
            const size_t i0 = (size_t)coff + (size_t)r * ldc + cb;
            const size_t i1 = (size_t)coff + (size_t)(r + 8) * ldc + cb;
            if (epilogue == 2) {
                o00 *= normcdff(o00); o01 *= normcdff(o01);
                o10 *= normcdff(o10); o11 *= normcdff(o11);
            } else if (epilogue == 3) {
                const float2 r0 = *(const float2*)(resid + i0);
                const float2 r1 = *(const float2*)(resid + i1);
                o00 += r0.x; o01 += r0.y; o10 += r1.x; o11 += r1.y;
            }
            *(float2*)(C + i0) = make_float2(o00, o01);
            *(float2*)(C + i1) = make_float2(o10, o11);
        }
    }
#undef STAGE_A
#undef STAGE_B
}

// ---------------------------------------------------------------------------
// LayerNorm over rows of length 1024. One block (256 threads) per row.
// ---------------------------------------------------------------------------
__global__ void __launch_bounds__(256)
ln_kernel(const float* __restrict__ x, const float* __restrict__ g,
          const float* __restrict__ b, float* __restrict__ out)
{
    const int row = blockIdx.x;
    const int tid = threadIdx.x;
    const float4 xv = ((const float4*)(x + (size_t)row * 1024))[tid];

    float s  = xv.x + xv.y + xv.z + xv.w;
    float ss = xv.x * xv.x + xv.y * xv.y + xv.z * xv.z + xv.w * xv.w;
#pragma unroll
    for (int o = 16; o; o >>= 1) {
        s  += __shfl_xor_sync(0xffffffffu, s, o);
        ss += __shfl_xor_sync(0xffffffffu, ss, o);
    }
    __shared__ float sm[16];
    if ((tid & 31) == 0) { sm[tid >> 5] = s; sm[8 + (tid >> 5)] = ss; }
    __syncthreads();
    float S = 0.f, SS = 0.f;
#pragma unroll
    for (int i = 0; i < 8; i++) { S += sm[i]; SS += sm[8 + i]; }
    const float mu  = S * (1.f / 1024.f);
    const float var = SS * (1.f / 1024.f) - mu * mu;
    const float rs  = rsqrtf(var + 1e-5f);

    const float4 gv = ((const float4*)g)[tid];
    const float4 bv = ((const float4*)b)[tid];
    float4 o;
    o.x = (xv.x - mu) * rs * gv.x + bv.x;
    o.y = (xv.y - mu) * rs * gv.y + bv.y;
    o.z = (xv.z - mu) * rs * gv.z + bv.z;
    o.w = (xv.w - mu) * rs * gv.w + bv.w;
    ((float4*)(out + (size_t)row * 1024))[tid] = o;
}

// ---------------------------------------------------------------------------
// Causal softmax with skewed relative bias (in-place on S).
// ---------------------------------------------------------------------------
__global__ void __launch_bounds__(256)
softmax_kernel(const float* __restrict__ S, const float* __restrict__ E,
               float* __restrict__ P)
{
    const int q  = blockIdx.x;
    const int bh = blockIdx.y;
    const size_t base = ((size_t)bh * 1024 + q) * 1024;
    const int tid = threadIdx.x;
    const float scale = 0.08838834764831845f;  // 1/sqrt(128)

    float v[4];
    float mx = -3.4e38f;
#pragma unroll
    for (int i = 0; i < 4; i++) {
        const int k = tid + i * 256;
        float val = -3.4e38f;
        if (k <= q) val = (S[base + k] + E[base + k - q + 1023]) * scale;
        v[i] = val;
        mx = fmaxf(mx, val);
    }
#pragma unroll
    for (int o = 16; o; o >>= 1) mx = fmaxf(mx, __shfl_xor_sync(0xffffffffu, mx, o));
    __shared__ float red[8];
    if ((tid & 31) == 0) red[tid >> 5] = mx;
    __syncthreads();
    float m2 = red[0];
#pragma unroll
    for (int i = 1; i < 8; i++) m2 = fmaxf(m2, red[i]);
    __syncthreads();

    float sum = 0.f;
#pragma unroll
    for (int i = 0; i < 4; i++) {
        const float e = (v[i] > -1e37f) ? expf(v[i] - m2) : 0.f;
        v[i] = e;
        sum += e;
    }
#pragma unroll
    for (int o = 16; o; o >>= 1) sum += __shfl_xor_sync(0xffffffffu, sum, o);
    if ((tid & 31) == 0) red[tid >> 5] = sum;
    __syncthreads();
    float tot = 0.f;
#pragma unroll
    for (int i = 0; i < 8; i++) tot += red[i];
    const float inv = 1.f / tot;
#pragma unroll
    for (int i = 0; i < 4; i++) {
        const int k = tid + i * 256;
        P[base + k] = v[i] * inv;
    }
}

// ---------------------------------------------------------------------------
extern "C" void kernel_launch(void* const* d_in, const int* in_sizes, int n_in,
                              void* d_out, int out_size)
{
    (void)in_sizes; (void)n_in; (void)out_size;
    const float* x      = (const float*)d_in[0];
    const float* W_qkv  = (const float*)d_in[1];
    const float* b_qkv  = (const float*)d_in[2];
    const float* W_o    = (const float*)d_in[3];
    const float* b_o    = (const float*)d_in[4];
    const float* Er     = (const float*)d_in[5];
    const float* ln1_g  = (const float*)d_in[6];
    const float* ln1_b  = (const float*)d_in[7];
    const float* ln2_g  = (const float*)d_in[8];
    const float* ln2_b  = (const float*)d_in[9];
    const float* W_fc   = (const float*)d_in[10];
    const float* b_fc   = (const float*)d_in[11];
    const float* W_proj = (const float*)d_in[12];
    const float* b_proj = (const float*)d_in[13];
    float* out = (float*)d_out;

    float *ln, *qkv, *sc, *qer, *yb, *hb;
    cudaGetSymbolAddress((void**)&ln,  g_ln);
    cudaGetSymbolAddress((void**)&qkv, g_qkv);
    cudaGetSymbolAddress((void**)&sc,  g_scores);
    cudaGetSymbolAddress((void**)&qer, g_qer);
    cudaGetSymbolAddress((void**)&yb,  g_y);
    cudaGetSymbolAddress((void**)&hb,  g_h);

    const long long sq_hi = 1024LL * 3072;      // per-b stride inside qkv
    const long long sq_lo = 128LL;               // per-head stride inside qkv
    const long long ss_hi = 8LL * 1024 * 1024;   // per-b stride in scores/qer
    const long long ss_lo = 1024LL * 1024;       // per-head stride

    // 1) LN1
    ln_kernel<<<8192, 256>>>(x, ln1_g, ln1_b, ln);

    // 2) QKV = ln @ W_qkv + b_qkv          (8192 x 3072 x 1024)
    gemm_tf32<false><<<dim3(24, 64, 1), 256>>>(
        ln, 1024, 0, 0, W_qkv, 3072, 0, 0, qkv, 3072, 0, 0,
        3072, 1024, b_qkv, nullptr, 1, 0);

    // 3) QEr[bh] = q @ Er^T                (batched 64, anti-tri skip)
    gemm_tf32<true><<<dim3(8, 8, 64), 256>>>(
        qkv, 3072, sq_hi, sq_lo, Er, 128, 0, 0, qer, 1024, ss_hi, ss_lo,
        1024, 128, nullptr, nullptr, 0, 2);

    // 4) S[bh] = q @ k^T                   (batched 64, lower-tri only)
    gemm_tf32<true><<<dim3(8, 8, 64), 256>>>(
        qkv, 3072, sq_hi, sq_lo, qkv + 1024, 3072, sq_hi, sq_lo, sc, 1024, ss_hi, ss_lo,
        1024, 128, nullptr, nullptr, 0, 1);

    // 5) P = causal softmax((S + skew(QEr)) / sqrt(hs))   (in-place)
    softmax_kernel<<<dim3(1024, 64), 256>>>(sc, qer, sc);

    // 6) y[bh] = P @ v                     (batched 64, causal K bound)
    gemm_tf32<false><<<dim3(1, 8, 64), 256>>>(
        sc, 1024, ss_hi, ss_lo, qkv + 2048, 3072, sq_hi, sq_lo,
        yb, 1024, 1024LL * 1024, 128,
        128, 1024, nullptr, nullptr, 0, 3);

    // 7) x1 = x + y @ W_o + b_o            (8192 x 1024 x 1024) -> d_out
    gemm_tf32<false><<<dim3(8, 64, 1), 256>>>(
        yb, 1024, 0, 0, W_o, 1024, 0, 0, out, 1024, 0, 0,
        1024, 1024, b_o, x, 3, 0);

    // 8) LN2
    ln_kernel<<<8192, 256>>>(out, ln2_g, ln2_b, ln);

    // 9) h = gelu(ln @ W_fc + b_fc)        (8192 x 4096 x 1024)
    gemm_tf32<false><<<dim3(32, 64, 1), 256>>>(
        ln, 1024, 0, 0, W_fc, 4096, 0, 0, hb, 4096, 0, 0,
        4096, 1024, b_fc, nullptr, 2, 0);

    // 10) out = x1 + h @ W_proj + b_proj   (8192 x 1024 x 4096)
    gemm_tf32<false><<<dim3(8, 64, 1), 256>>>(
        hb, 4096, 0, 0, W_proj, 1024, 0, 0, out, 1024, 0, 0,
        1024, 4096, b_proj, out, 3, 0);
}

// round 4
// speedup vs baseline: 1.2679x; 1.2679x over previous
#include <cuda_runtime.h>
#include <math.h>
#include <stdint.h>

// Problem constants: B=8, L=1024, D=1024, F=4096, nh=8, hs=128, M=B*L=8192
#define BM 128
#define BN 128
#define BKt 16

// Scratch (static device globals; no runtime allocation)
__device__ float g_ln[8388608];        // 8192*1024   LN output
__device__ float g_qkv[25165824];      // 8192*3072   QKV
__device__ float g_scores[67108864];   // 64*1024*1024  S then P
__device__ float g_qer[67108864];      // 64*1024*1024  QEr
__device__ float g_y[8388608];         // 8192*1024   attention output
__device__ float g_h[33554432];        // 8192*4096   MLP hidden

__device__ __forceinline__ uint32_t f2tf(float x) {
    uint32_t u;
    asm("cvt.rna.tf32.f32 %0, %1;" : "=r"(u) : "f"(x));
    return u;
}

__device__ __forceinline__ void mma_tf32(float c[4],
    uint32_t a0, uint32_t a1, uint32_t a2, uint32_t a3,
    uint32_t b0, uint32_t b1)
{
    asm volatile(
        "mma.sync.aligned.m16n8k8.row.col.f32.tf32.tf32.f32 "
        "{%0,%1,%2,%3}, {%4,%5,%6,%7}, {%8,%9}, {%0,%1,%2,%3};"
        : "+f"(c[0]), "+f"(c[1]), "+f"(c[2]), "+f"(c[3])
        : "r"(a0), "r"(a1), "r"(a2), "r"(a3), "r"(b0), "r"(b1));
}

// ---------------------------------------------------------------------------
// tf32 tensor-core GEMM, double-buffered smem (one __syncthreads per k-tile).
//   TRANSB=false: B is KxN row-major.  TRANSB=true: B is NxK row-major.
// Batched via blockIdx.z: z -> hi=z/8, lo=z%8.
// epilogue: 0=none, 1=+bias, 2=+bias+GELU, 3=+bias+residual
// tri: 0=full, 1=lower-tri tile skip, 2=anti-tri tile skip, 3=causal K bound
// Block tile 128x128, k-step 16; 8 warps as 2(m) x 4(n), warp tile 64x32.
// ---------------------------------------------------------------------------
template <bool TRANSB>
__global__ void __launch_bounds__(256, 2)
gemm_tf32(const float* __restrict__ A, int lda, long long sAhi, long long sAlo,
          const float* __restrict__ Bm, int ldb, long long sBhi, long long sBlo,
          float* __restrict__ C, int ldc, long long sChi, long long sClo,
          int N, int K,
          const float* __restrict__ bias, const float* __restrict__ resid,
          int epilogue, int tri)
{
    const int n0 = blockIdx.x * BN;
    const int m0 = blockIdx.y * BM;
    if (tri == 1 && n0 > m0) return;
    if (tri == 2 && (m0 + n0) < (N - BM - BN + 1)) return;
    const int kmax = (tri == 3) ? min(K, m0 + BM) : K;

    const int z = blockIdx.z, hi = z >> 3, lo = z & 7;
    A  += hi * sAhi + lo * sAlo;
    Bm += hi * sBhi + lo * sBlo;
    const long long coff = hi * sChi + lo * sClo;

    // Ping-pong buffers.
    //   As[p][r][k ^ (((r>>1)&3)<<2)]   (A as [m][k], 16 k per row)
    //   Bs[p][k][n ^ ((k&3)<<3)]        (B as [k][n], 128 n per row)
    __shared__ uint32_t As[2][128][16];
    __shared__ uint32_t Bs[2][16][128];

    const int tid  = threadIdx.x;
    const int lane = tid & 31;
    const int warp = tid >> 5;
    const int g  = lane >> 2;   // 0..7
    const int tg = lane & 3;    // 0..3
    const int wm = (warp >> 2) * 64;
    const int wn = (warp & 3) * 32;

    // A staging: row ra, k-half ka
    const int ra = tid >> 1;
    const int ka = (tid & 1) * 8;
    const float* Ap = A + (size_t)(m0 + ra) * lda + ka;

    // B staging
    int rb, kb;
    const float* Bp;
    if (TRANSB) {               // B row-major NxK: load along k
        rb = tid >> 1;          // n index 0..127
        kb = (tid & 1) * 8;     // k-half
        Bp = Bm + (size_t)(n0 + rb) * ldb + kb;
    } else {                    // B row-major KxN: load along n
        rb = tid >> 4;          // k row 0..15
        kb = (tid & 15) * 8;    // n offset
        Bp = Bm + (size_t)rb * ldb + n0 + kb;
    }

    float4 aR0, aR1, bR0, bR1;
    float acc[4][4][4] = {};

#define STAGE_A(p) do { \
        const int msk = ((ra >> 1) & 3) << 2; \
        uint32_t* d0 = &As[p][ra][ka ^ msk]; \
        d0[0] = f2tf(aR0.x); d0[1] = f2tf(aR0.y); d0[2] = f2tf(aR0.z); d0[3] = f2tf(aR0.w); \
        uint32_t* d1 = &As[p][ra][(ka + 8) ^ msk]; \
        d1[0] = f2tf(aR1.x); d1[1] = f2tf(aR1.y); d1[2] = f2tf(aR1.z); d1[3] = f2tf(aR1.w); \
    } while (0)
    // NOTE: (ka+8)^msk vs (ka+4)^msk — see below; we keep round-2 exact indexing:
#undef STAGE_A
#define STAGE_A(p) do { \
        const int msk = ((ra >> 1) & 3) << 2; \
        uint32_t* d0 = &As[p][ra][ka ^ msk]; \
        d0[0] = f2tf(aR0.x); d0[1] = f2tf(aR0.y); d0[2] = f2tf(aR0.z); d0[3] = f2tf(aR0.w); \
        uint32_t* d1 = &As[p][ra][(ka + 4) ^ msk]; \
        d1[0] = f2tf(aR1.x); d1[1] = f2tf(aR1.y); d1[2] = f2tf(aR1.z); d1[3] = f2tf(aR1.w); \
    } while (0)

#define STAGE_B(p) do { \
        if (TRANSB) { \
            float v[8] = {bR0.x, bR0.y, bR0.z, bR0.w, bR1.x, bR1.y, bR1.z, bR1.w}; \
            _Pragma("unroll") \
            for (int e = 0; e < 8; e++) { \
                const int k = kb + e; \
                Bs[p][k][rb ^ ((k & 3) << 3)] = f2tf(v[e]); \
            } \
        } else { \
            const int msk = (rb & 3) << 3; \
            uint32_t* d0 = &Bs[p][rb][kb ^ msk]; \
            d0[0] = f2tf(bR0.x); d0[1] = f2tf(bR0.y); d0[2] = f2tf(bR0.z); d0[3] = f2tf(bR0.w); \
            uint32_t* d1 = &Bs[p][rb][(kb + 4) ^ msk]; \
            d1[0] = f2tf(bR1.x); d1[1] = f2tf(bR1.y); d1[2] = f2tf(bR1.z); d1[3] = f2tf(bR1.w); \
        } \
    } while (0)

    // prologue: stage tile 0 into buffer 0
    aR0 = *(const float4*)(Ap);
    aR1 = *(const float4*)(Ap + 4);
    bR0 = *(const float4*)(Bp);
    bR1 = *(const float4*)(Bp + 4);
    STAGE_A(0);
    STAGE_B(0);
    __syncthreads();

    int p = 0;
    for (int k0 = 0; k0 < kmax; k0 += BKt) {
        const bool nxt = (k0 + BKt) < kmax;
        if (nxt) {
            aR0 = *(const float4*)(Ap + k0 + BKt);
            aR1 = *(const float4*)(Ap + k0 + BKt + 4);
            if (TRANSB) {
                bR0 = *(const float4*)(Bp + k0 + BKt);
                bR1 = *(const float4*)(Bp + k0 + BKt + 4);
            } else {
                bR0 = *(const float4*)(Bp + (size_t)(k0 + BKt) * ldb);
                bR1 = *(const float4*)(Bp + (size_t)(k0 + BKt) * ldb + 4);
            }
        }
#pragma unroll
        for (int k8 = 0; k8 < 16; k8 += 8) {
            uint32_t af[4][4], bf[4][2];
#pragma unroll
            for (int mt = 0; mt < 4; mt++) {
                const int r0 = wm + mt * 16 + g;
                const int r1 = r0 + 8;
                const int kk = k8 + tg;
                const int m0k = ((r0 >> 1) & 3) << 2;
                af[mt][0] = As[p][r0][kk ^ m0k];
                af[mt][1] = As[p][r1][kk ^ m0k];
                af[mt][2] = As[p][r0][(kk + 4) ^ m0k];
                af[mt][3] = As[p][r1][(kk + 4) ^ m0k];
            }
#pragma unroll
            for (int nt = 0; nt < 4; nt++) {
                const int n = wn + nt * 8 + g;
                bf[nt][0] = Bs[p][k8 + tg][n ^ (tg << 3)];
                bf[nt][1] = Bs[p][k8 + tg + 4][n ^ (tg << 3)];
            }
#pragma unroll
            for (int mt = 0; mt < 4; mt++)
#pragma unroll
                for (int nt = 0; nt < 4; nt++)
                    mma_tf32(acc[mt][nt],
                             af[mt][0], af[mt][1], af[mt][2], af[mt][3],
                             bf[nt][0], bf[nt][1]);
        }
        if (nxt) {
            STAGE_A(p ^ 1);
            STAGE_B(p ^ 1);
            __syncthreads();
        }
        p ^= 1;
    }

    // Epilogue
#pragma unroll
    for (int mt = 0; mt < 4; mt++) {
#pragma unroll
        for (int nt = 0; nt < 4; nt++) {
            const int r  = m0 + wm + mt * 16 + g;
            const int cb = n0 + wn + nt * 8 + tg * 2;
            float b0 = 0.f, b1 = 0.f;
            if (epilogue) { b0 = bias[cb]; b1 = bias[cb + 1]; }
            float o00 = acc[mt][nt][0] + b0, o01 = acc[mt][nt][1] + b1;
            float o10 = acc[mt][nt][2] + b0, o11 = acc[mt][nt][3] + b1;
            const size_t i0 = (size_t)coff + (size_t)r * ldc + cb;
            const size_t i1 = (size_t)coff + (size_t)(r + 8) * ldc + cb;
            if (epilogue == 2) {
                o00 *= normcdff(o00); o01 *= normcdff(o01);
                o10 *= normcdff(o10); o11 *= normcdff(o11);
            } else if (epilogue == 3) {
                const float2 r0 = *(const float2*)(resid + i0);
                const float2 r1 = *(const float2*)(resid + i1);
                o00 += r0.x; o01 += r0.y; o10 += r1.x; o11 += r1.y;
            }
            *(float2*)(C + i0) = make_float2(o00, o01);
            *(float2*)(C + i1) = make_float2(o10, o11);
        }
    }
#undef STAGE_A
#undef STAGE_B
}

// ---------------------------------------------------------------------------
// LayerNorm over rows of length 1024. One block (256 threads) per row.
// ---------------------------------------------------------------------------
__global__ void __launch_bounds__(256)
ln_kernel(const float* __restrict__ x, const float* __restrict__ g,
          const float* __restrict__ b, float* __restrict__ out)
{
    const int row = blockIdx.x;
    const int tid = threadIdx.x;
    const float4 xv = ((const float4*)(x + (size_t)row * 1024))[tid];

    float s  = xv.x + xv.y + xv.z + xv.w;
    float ss = xv.x * xv.x + xv.y * xv.y + xv.z * xv.z + xv.w * xv.w;
#pragma unroll
    for (int o = 16; o; o >>= 1) {
        s  += __shfl_xor_sync(0xffffffffu, s, o);
        ss += __shfl_xor_sync(0xffffffffu, ss, o);
    }
    __shared__ float sm[16];
    if ((tid & 31) == 0) { sm[tid >> 5] = s; sm[8 + (tid >> 5)] = ss; }
    __syncthreads();
    float S = 0.f, SS = 0.f;
#pragma unroll
    for (int i = 0; i < 8; i++) { S += sm[i]; SS += sm[8 + i]; }
    const float mu  = S * (1.f / 1024.f);
    const float var = SS * (1.f / 1024.f) - mu * mu;
    const float rs  = rsqrtf(var + 1e-5f);

    const float4 gv = ((const float4*)g)[tid];
    const float4 bv = ((const float4*)b)[tid];
    float4 o;
    o.x = (xv.x - mu) * rs * gv.x + bv.x;
    o.y = (xv.y - mu) * rs * gv.y + bv.y;
    o.z = (xv.z - mu) * rs * gv.z + bv.z;
    o.w = (xv.w - mu) * rs * gv.w + bv.w;
    ((float4*)(out + (size_t)row * 1024))[tid] = o;
}

// ---------------------------------------------------------------------------
// Causal softmax with skewed relative bias (in-place on S).
// ---------------------------------------------------------------------------
__global__ void __launch_bounds__(256)
softmax_kernel(const float* __restrict__ S, const float* __restrict__ E,
               float* __restrict__ P)
{
    const int q  = blockIdx.x;
    const int bh = blockIdx.y;
    const size_t base = ((size_t)bh * 1024 + q) * 1024;
    const int tid = threadIdx.x;
    const float scale = 0.08838834764831845f;  // 1/sqrt(128)

    float v[4];
    float mx = -3.4e38f;
#pragma unroll
    for (int i = 0; i < 4; i++) {
        const int k = tid + i * 256;
        float val = -3.4e38f;
        if (k <= q) val = (S[base + k] + E[base + k - q + 1023]) * scale;
        v[i] = val;
        mx = fmaxf(mx, val);
    }
#pragma unroll
    for (int o = 16; o; o >>= 1) mx = fmaxf(mx, __shfl_xor_sync(0xffffffffu, mx, o));
    __shared__ float red[8];
    if ((tid & 31) == 0) red[tid >> 5] = mx;
    __syncthreads();
    float m2 = red[0];
#pragma unroll
    for (int i = 1; i < 8; i++) m2 = fmaxf(m2, red[i]);
    __syncthreads();

    float sum = 0.f;
#pragma unroll
    for (int i = 0; i < 4; i++) {
        const float e = (v[i] > -1e37f) ? expf(v[i] - m2) : 0.f;
        v[i] = e;
        sum += e;
    }
#pragma unroll
    for (int o = 16; o; o >>= 1) sum += __shfl_xor_sync(0xffffffffu, sum, o);
    if ((tid & 31) == 0) red[tid >> 5] = sum;
    __syncthreads();
    float tot = 0.f;
#pragma unroll
    for (int i = 0; i < 8; i++) tot += red[i];
    const float inv = 1.f / tot;
#pragma unroll
    for (int i = 0; i < 4; i++) {
        const int k = tid + i * 256;
        P[base + k] = v[i] * inv;
    }
}

// ---------------------------------------------------------------------------
extern "C" void kernel_launch(void* const* d_in, const int* in_sizes, int n_in,
                              void* d_out, int out_size)
{
    (void)in_sizes; (void)n_in; (void)out_size;
    const float* x      = (const float*)d_in[0];
    const float* W_qkv  = (const float*)d_in[1];
    const float* b_qkv  = (const float*)d_in[2];
    const float* W_o    = (const float*)d_in[3];
    const float* b_o    = (const float*)d_in[4];
    const float* Er     = (const float*)d_in[5];
    const float* ln1_g  = (const float*)d_in[6];
    const float* ln1_b  = (const float*)d_in[7];
    const float* ln2_g  = (const float*)d_in[8];
    const float* ln2_b  = (const float*)d_in[9];
    const float* W_fc   = (const float*)d_in[10];
    const float* b_fc   = (const float*)d_in[11];
    const float* W_proj = (const float*)d_in[12];
    const float* b_proj = (const float*)d_in[13];
    float* out = (float*)d_out;

    float *ln, *qkv, *sc, *qer, *yb, *hb;
    cudaGetSymbolAddress((void**)&ln,  g_ln);
    cudaGetSymbolAddress((void**)&qkv, g_qkv);
    cudaGetSymbolAddress((void**)&sc,  g_scores);
    cudaGetSymbolAddress((void**)&qer, g_qer);
    cudaGetSymbolAddress((void**)&yb,  g_y);
    cudaGetSymbolAddress((void**)&hb,  g_h);

    const long long sq_hi = 1024LL * 3072;      // per-b stride inside qkv
    const long long sq_lo = 128LL;               // per-head stride inside qkv
    const long long ss_hi = 8LL * 1024 * 1024;   // per-b stride in scores/qer
    const long long ss_lo = 1024LL * 1024;       // per-head stride

    // 1) LN1
    ln_kernel<<<8192, 256>>>(x, ln1_g, ln1_b, ln);

    // 2) QKV = ln @ W_qkv + b_qkv          (8192 x 3072 x 1024)
    gemm_tf32<false><<<dim3(24, 64, 1), 256>>>(
        ln, 1024, 0, 0, W_qkv, 3072, 0, 0, qkv, 3072, 0, 0,
        3072, 1024, b_qkv, nullptr, 1, 0);

    // 3) QEr[bh] = q @ Er^T                (batched 64, anti-tri skip)
    gemm_tf32<true><<<dim3(8, 8, 64), 256>>>(
        qkv, 3072, sq_hi, sq_lo, Er, 128, 0, 0, qer, 1024, ss_hi, ss_lo,
        1024, 128, nullptr, nullptr, 0, 2);

    // 4) S[bh] = q @ k^T                   (batched 64, lower-tri only)
    gemm_tf32<true><<<dim3(8, 8, 64), 256>>>(
        qkv, 3072, sq_hi, sq_lo, qkv + 1024, 3072, sq_hi, sq_lo, sc, 1024, ss_hi, ss_lo,
        1024, 128, nullptr, nullptr, 0, 1);

    // 5) P = causal softmax((S + skew(QEr)) / sqrt(hs))   (in-place)
    softmax_kernel<<<dim3(1024, 64), 256>>>(sc, qer, sc);

    // 6) y[bh] = P @ v                     (batched 64, causal K bound)
    gemm_tf32<false><<<dim3(1, 8, 64), 256>>>(
        sc, 1024, ss_hi, ss_lo, qkv + 2048, 3072, sq_hi, sq_lo,
        yb, 1024, 1024LL * 1024, 128,
        128, 1024, nullptr, nullptr, 0, 3);

    // 7) x1 = x + y @ W_o + b_o            (8192 x 1024 x 1024) -> d_out
    gemm_tf32<false><<<dim3(8, 64, 1), 256>>>(
        yb, 1024, 0, 0, W_o, 1024, 0, 0, out, 1024, 0, 0,
        1024, 1024, b_o, x, 3, 0);

    // 8) LN2
    ln_kernel<<<8192, 256>>>(out, ln2_g, ln2_b, ln);

    // 9) h = gelu(ln @ W_fc + b_fc)        (8192 x 4096 x 1024)
    gemm_tf32<false><<<dim3(32, 64, 1), 256>>>(
        ln, 1024, 0, 0, W_fc, 4096, 0, 0, hb, 4096, 0, 0,
        4096, 1024, b_fc, nullptr, 2, 0);

    // 10) out = x1 + h @ W_proj + b_proj   (8192 x 1024 x 4096)
    gemm_tf32<false><<<dim3(8, 64, 1), 256>>>(
        hb, 4096, 0, 0, W_proj, 1024, 0, 0, out, 1024, 0, 0,
        1024, 4096, b_proj, out, 3, 0);
}

// round 6
// speedup vs baseline: 1.7350x; 1.3683x over previous
#include <cuda_runtime.h>
#include <math.h>
#include <stdint.h>

// Problem constants: B=8, L=1024, D=1024, F=4096, nh=8, hs=128, M=B*L=8192

// Scratch (static device globals; no runtime allocation)
__device__ float g_ln[8388608];        // 8192*1024   LN output (tf32-rounded)
__device__ float g_qkv[25165824];      // 8192*3072   QKV (tf32-rounded)
__device__ float g_scores[67108864];   // 64*1024*1024  S then P (rounded)
__device__ float g_qer[67108864];      // 64*1024*1024  QEr
__device__ float g_y[8388608];         // 8192*1024   attn out (rounded)
__device__ float g_h[33554432];        // 8192*4096   MLP hidden (rounded)
__device__ float g_wq[3145728];        // W_qkv rounded
__device__ float g_wo[1048576];        // W_o rounded
__device__ float g_wf[4194304];        // W_fc rounded
__device__ float g_wp[4194304];        // W_proj rounded
__device__ float g_er[131072];         // Er rounded

__device__ __forceinline__ uint32_t f2tf(float x) {
    uint32_t u;
    asm("cvt.rna.tf32.f32 %0, %1;" : "=r"(u) : "f"(x));
    return u;
}
__device__ __forceinline__ float rtf(float x) { return __uint_as_float(f2tf(x)); }

__device__ __forceinline__ uint32_t smem_u32(const void* p) {
    uint32_t a;
    asm("{ .reg .u64 t; cvta.to.shared.u64 t, %1; cvt.u32.u64 %0, t; }" : "=r"(a) : "l"(p));
    return a;
}
__device__ __forceinline__ void cpa16(uint32_t dst, const float* src) {
    asm volatile("cp.async.cg.shared.global [%0], [%1], 16;\n" :: "r"(dst), "l"(src));
}
#define CPA_COMMIT() asm volatile("cp.async.commit_group;\n" ::: "memory")
#define CPA_WAIT1()  asm volatile("cp.async.wait_group 1;\n" ::: "memory")

__device__ __forceinline__ void mma_tf32(float c[4],
    uint32_t a0, uint32_t a1, uint32_t a2, uint32_t a3,
    uint32_t b0, uint32_t b1)
{
    asm volatile(
        "mma.sync.aligned.m16n8k8.row.col.f32.tf32.tf32.f32 "
        "{%0,%1,%2,%3}, {%4,%5,%6,%7}, {%8,%9}, {%0,%1,%2,%3};"
        : "+f"(c[0]), "+f"(c[1]), "+f"(c[2]), "+f"(c[3])
        : "r"(a0), "r"(a1), "r"(a2), "r"(a3), "r"(b0), "r"(b1));
}

// ---------------------------------------------------------------------------
// tf32 mma.sync GEMM, 3-stage cp.async pipeline. Inputs must be pre-rounded
// to tf32 (bit patterns pass straight through cp.async into the MMA).
//   TRANSB=false: B is KxN row-major.  TRANSB=true: B is NxK row-major.
// Block tile 128x128, k-step 16; 8 warps (2m x 4n), warp tile 64x32.
// Batched via blockIdx.z: hi=z>>3, lo=z&7.
// epilogue: 0=none, 1=+bias, 2=+bias+GELU, 3=+bias+residual
// tri: 0=full, 1=lower-tri tile skip, 2=anti-tri tile skip, 3=causal K bound
// rnd: round outputs to tf32 (for tensors feeding later GEMMs)
// ---------------------------------------------------------------------------
template <bool TRANSB>
__global__ void __launch_bounds__(256, 2)
gemm_tf32(const float* __restrict__ A, int lda, long long sAhi, long long sAlo,
          const float* __restrict__ Bm, int ldb, long long sBhi, long long sBlo,
          float* __restrict__ C, int ldc, long long sChi, long long sClo,
          int N, int K,
          const float* __restrict__ bias, const float* __restrict__ resid,
          int epilogue, int tri, int rnd)
{
    const int n0 = blockIdx.x * 128;
    const int m0 = blockIdx.y * 128;
    if (tri == 1 && n0 > m0) return;
    if (tri == 2 && (m0 + n0) < (N - 255)) return;
    const int kmax = (tri == 3) ? min(K, m0 + 128) : K;
    const int ns = kmax >> 4;    // k-tiles of 16

    const int z = blockIdx.z, hi = z >> 3, lo = z & 7;
    A  += hi * sAhi + lo * sAlo;
    Bm += hi * sBhi + lo * sBlo;
    const long long coff = hi * sChi + lo * sClo;

    // 3-stage buffers (exactly 48KB static):
    //   As[p]: [r:128][k:16]  with k ^ (((r>>1)&3)<<2)
    //   Bs[p] TRANSB : [n:128][k:16]  with k ^ (((n>>1)&3)<<2)
    //   Bs[p] !TRANSB: [k:16][n:128]  with n ^ ((k&3)<<3)
    __shared__ uint32_t As[3 * 2048];
    __shared__ uint32_t Bs[3 * 2048];

    const int tid  = threadIdx.x;
    const int lane = tid & 31;
    const int warp = tid >> 5;
    const int g  = lane >> 2;   // 0..7
    const int tg = lane & 3;    // 0..3
    const int wm = (warp >> 2) * 64;
    const int wn = (warp & 3) * 32;

    const uint32_t aBase = smem_u32(As);
    const uint32_t bBase = smem_u32(Bs);

    // ---- staging offsets (bytes) ----
    const int ra  = tid >> 1;
    const int ka  = (tid & 1) * 8;
    const int mskA = ((ra >> 1) & 3) << 2;
    const uint32_t aoff0 = (uint32_t)(ra * 16 + (ka ^ mskA)) * 4u;
    const uint32_t aoff1 = (uint32_t)(ra * 16 + ((ka + 4) ^ mskA)) * 4u;
    const float* Ap = A + (size_t)(m0 + ra) * lda + ka;

    uint32_t boff0, boff1;
    const float* Bp;
    if (TRANSB) {
        const int rb = tid >> 1;
        const int kb = (tid & 1) * 8;
        const int mskB = ((rb >> 1) & 3) << 2;
        boff0 = (uint32_t)(rb * 16 + (kb ^ mskB)) * 4u;
        boff1 = (uint32_t)(rb * 16 + ((kb + 4) ^ mskB)) * 4u;
        Bp = Bm + (size_t)(n0 + rb) * ldb + kb;
    } else {
        const int rb = tid >> 4;           // k row 0..15
        const int nb = (tid & 15) * 8;     // n offset
        const int mskB = (rb & 3) << 3;
        boff0 = (uint32_t)(rb * 128 + (nb ^ mskB)) * 4u;
        boff1 = (uint32_t)(rb * 128 + ((nb + 4) ^ mskB)) * 4u;
        Bp = Bm + (size_t)rb * ldb + n0 + nb;
    }

#define STAGE(s_, p_) do { \
        const int k0_ = (s_) << 4; \
        const uint32_t da_ = aBase + (uint32_t)(p_) * 8192u; \
        const uint32_t db_ = bBase + (uint32_t)(p_) * 8192u; \
        const float* ga_ = Ap + k0_; \
        cpa16(da_ + aoff0, ga_); \
        cpa16(da_ + aoff1, ga_ + 4); \
        if (TRANSB) { \
            const float* gb_ = Bp + k0_; \
            cpa16(db_ + boff0, gb_); \
            cpa16(db_ + boff1, gb_ + 4); \
        } else { \
            const float* gb_ = Bp + (size_t)k0_ * ldb; \
            cpa16(db_ + boff0, gb_); \
            cpa16(db_ + boff1, gb_ + 4); \
        } \
    } while (0)

    float acc[4][4][4] = {};

    STAGE(0, 0); CPA_COMMIT();
    STAGE(1, 1); CPA_COMMIT();

    int p = 0;
    for (int s = 0; s < ns; s++) {
        CPA_WAIT1();
        __syncthreads();
        const uint32_t* Ap_s = As + p * 2048;
        const uint32_t* Bp_s = Bs + p * 2048;
#pragma unroll
        for (int k8 = 0; k8 < 16; k8 += 8) {
            uint32_t af[4][4], bf[4][2];
            const int kk = k8 + tg;
#pragma unroll
            for (int mt = 0; mt < 4; mt++) {
                const int r0 = wm + mt * 16 + g;
                const int msk = ((r0 >> 1) & 3) << 2;
                af[mt][0] = Ap_s[r0 * 16 + (kk ^ msk)];
                af[mt][1] = Ap_s[(r0 + 8) * 16 + (kk ^ msk)];
                af[mt][2] = Ap_s[r0 * 16 + ((kk + 4) ^ msk)];
                af[mt][3] = Ap_s[(r0 + 8) * 16 + ((kk + 4) ^ msk)];
            }
#pragma unroll
            for (int nt = 0; nt < 4; nt++) {
                const int n = wn + nt * 8 + g;
                if (TRANSB) {
                    const int msk = ((n >> 1) & 3) << 2;
                    bf[nt][0] = Bp_s[n * 16 + (kk ^ msk)];
                    bf[nt][1] = Bp_s[n * 16 + ((kk + 4) ^ msk)];
                } else {
                    bf[nt][0] = Bp_s[(k8 + tg) * 128 + (n ^ (tg << 3))];
                    bf[nt][1] = Bp_s[(k8 + tg + 4) * 128 + (n ^ (tg << 3))];
                }
            }
#pragma unroll
            for (int mt = 0; mt < 4; mt++)
#pragma unroll
                for (int nt = 0; nt < 4; nt++)
                    mma_tf32(acc[mt][nt],
                             af[mt][0], af[mt][1], af[mt][2], af[mt][3],
                             bf[nt][0], bf[nt][1]);
        }
        if (s + 2 < ns) {
            const int p2 = (p + 2 >= 3) ? (p + 2 - 3) : (p + 2);
            STAGE(s + 2, p2);
        }
        CPA_COMMIT();
        p = (p + 1 == 3) ? 0 : (p + 1);
    }

    // Epilogue
#pragma unroll
    for (int mt = 0; mt < 4; mt++) {
#pragma unroll
        for (int nt = 0; nt < 4; nt++) {
            const int r  = m0 + wm + mt * 16 + g;
            const int cb = n0 + wn + nt * 8 + tg * 2;
            float b0 = 0.f, b1 = 0.f;
            if (epilogue) { b0 = bias[cb]; b1 = bias[cb + 1]; }
            float o00 = acc[mt][nt][0] + b0, o01 = acc[mt][nt][1] + b1;
            float o10 = acc[mt][nt][2] + b0, o11 = acc[mt][nt][3] + b1;
            const size_t i0 = (size_t)coff + (size_t)r * ldc + cb;
            const size_t i1 = (size_t)coff + (size_t)(r + 8) * ldc + cb;
            if (epilogue == 2) {
                o00 *= normcdff(o00); o01 *= normcdff(o01);
                o10 *= normcdff(o10); o11 *= normcdff(o11);
            } else if (epilogue == 3) {
                const float2 r0 = *(const float2*)(resid + i0);
                const float2 r1 = *(const float2*)(resid + i1);
                o00 += r0.x; o01 += r0.y; o10 += r1.x; o11 += r1.y;
            }
            if (rnd) { o00 = rtf(o00); o01 = rtf(o01); o10 = rtf(o10); o11 = rtf(o11); }
            *(float2*)(C + i0) = make_float2(o00, o01);
            *(float2*)(C + i1) = make_float2(o10, o11);
        }
    }
#undef STAGE
}

// ---------------------------------------------------------------------------
// Round-copy to tf32 (vectorized): out[i] = rtf(in[i]), n multiple of 4.
// ---------------------------------------------------------------------------
__global__ void __launch_bounds__(256)
roundcopy4(const float4* __restrict__ in, float4* __restrict__ out, int n4)
{
    const int i = blockIdx.x * 256 + threadIdx.x;
    if (i < n4) {
        float4 v = in[i];
        v.x = rtf(v.x); v.y = rtf(v.y); v.z = rtf(v.z); v.w = rtf(v.w);
        out[i] = v;
    }
}

// ---------------------------------------------------------------------------
// LayerNorm (rows of 1024), output tf32-rounded (always feeds a GEMM).
// ---------------------------------------------------------------------------
__global__ void __launch_bounds__(256)
ln_kernel(const float* __restrict__ x, const float* __restrict__ g,
          const float* __restrict__ b, float* __restrict__ out)
{
    const int row = blockIdx.x;
    const int tid = threadIdx.x;
    const float4 xv = ((const float4*)(x + (size_t)row * 1024))[tid];

    float s  = xv.x + xv.y + xv.z + xv.w;
    float ss = xv.x * xv.x + xv.y * xv.y + xv.z * xv.z + xv.w * xv.w;
#pragma unroll
    for (int o = 16; o; o >>= 1) {
        s  += __shfl_xor_sync(0xffffffffu, s, o);
        ss += __shfl_xor_sync(0xffffffffu, ss, o);
    }
    __shared__ float sm[16];
    if ((tid & 31) == 0) { sm[tid >> 5] = s; sm[8 + (tid >> 5)] = ss; }
    __syncthreads();
    float S = 0.f, SS = 0.f;
#pragma unroll
    for (int i = 0; i < 8; i++) { S += sm[i]; SS += sm[8 + i]; }
    const float mu  = S * (1.f / 1024.f);
    const float var = SS * (1.f / 1024.f) - mu * mu;
    const float rs  = rsqrtf(var + 1e-5f);

    const float4 gv = ((const float4*)g)[tid];
    const float4 bv = ((const float4*)b)[tid];
    float4 o;
    o.x = rtf((xv.x - mu) * rs * gv.x + bv.x);
    o.y = rtf((xv.y - mu) * rs * gv.y + bv.y);
    o.z = rtf((xv.z - mu) * rs * gv.z + bv.z);
    o.w = rtf((xv.w - mu) * rs * gv.w + bv.w);
    ((float4*)(out + (size_t)row * 1024))[tid] = o;
}

// ---------------------------------------------------------------------------
// Causal softmax with skewed relative bias (in-place on S), output rounded.
// ---------------------------------------------------------------------------
__global__ void __launch_bounds__(256)
softmax_kernel(const float* __restrict__ S, const float* __restrict__ E,
               float* __restrict__ P)
{
    const int q  = blockIdx.x;
    const int bh = blockIdx.y;
    const size_t base = ((size_t)bh * 1024 + q) * 1024;
    const int tid = threadIdx.x;
    const float scale = 0.08838834764831845f;  // 1/sqrt(128)

    float v[4];
    float mx = -3.4e38f;
#pragma unroll
    for (int i = 0; i < 4; i++) {
        const int k = tid + i * 256;
        float val = -3.4e38f;
        if (k <= q) val = (S[base + k] + E[base + k - q + 1023]) * scale;
        v[i] = val;
        mx = fmaxf(mx, val);
    }
#pragma unroll
    for (int o = 16; o; o >>= 1) mx = fmaxf(mx, __shfl_xor_sync(0xffffffffu, mx, o));
    __shared__ float red[8];
    if ((tid & 31) == 0) red[tid >> 5] = mx;
    __syncthreads();
    float m2 = red[0];
#pragma unroll
    for (int i = 1; i < 8; i++) m2 = fmaxf(m2, red[i]);
    __syncthreads();

    float sum = 0.f;
#pragma unroll
    for (int i = 0; i < 4; i++) {
        const float e = (v[i] > -1e37f) ? expf(v[i] - m2) : 0.f;
        v[i] = e;
        sum += e;
    }
#pragma unroll
    for (int o = 16; o; o >>= 1) sum += __shfl_xor_sync(0xffffffffu, sum, o);
    if ((tid & 31) == 0) red[tid >> 5] = sum;
    __syncthreads();
    float tot = 0.f;
#pragma unroll
    for (int i = 0; i < 8; i++) tot += red[i];
    const float inv = 1.f / tot;
#pragma unroll
    for (int i = 0; i < 4; i++) {
        const int k = tid + i * 256;
        P[base + k] = rtf(v[i] * inv);
    }
}

// ---------------------------------------------------------------------------
extern "C" void kernel_launch(void* const* d_in, const int* in_sizes, int n_in,
                              void* d_out, int out_size)
{
    (void)in_sizes; (void)n_in; (void)out_size;
    const float* x      = (const float*)d_in[0];
    const float* W_qkv  = (const float*)d_in[1];
    const float* b_qkv  = (const float*)d_in[2];
    const float* W_o    = (const float*)d_in[3];
    const float* b_o    = (const float*)d_in[4];
    const float* Er     = (const float*)d_in[5];
    const float* ln1_g  = (const float*)d_in[6];
    const float* ln1_b  = (const float*)d_in[7];
    const float* ln2_g  = (const float*)d_in[8];
    const float* ln2_b  = (const float*)d_in[9];
    const float* W_fc   = (const float*)d_in[10];
    const float* b_fc   = (const float*)d_in[11];
    const float* W_proj = (const float*)d_in[12];
    const float* b_proj = (const float*)d_in[13];
    float* out = (float*)d_out;

    float *ln, *qkv, *sc, *qer, *yb, *hb, *wq, *wo, *wf, *wp, *er;
    cudaGetSymbolAddress((void**)&ln,  g_ln);
    cudaGetSymbolAddress((void**)&qkv, g_qkv);
    cudaGetSymbolAddress((void**)&sc,  g_scores);
    cudaGetSymbolAddress((void**)&qer, g_qer);
    cudaGetSymbolAddress((void**)&yb,  g_y);
    cudaGetSymbolAddress((void**)&hb,  g_h);
    cudaGetSymbolAddress((void**)&wq,  g_wq);
    cudaGetSymbolAddress((void**)&wo,  g_wo);
    cudaGetSymbolAddress((void**)&wf,  g_wf);
    cudaGetSymbolAddress((void**)&wp,  g_wp);
    cudaGetSymbolAddress((void**)&er,  g_er);

    const long long sq_hi = 1024LL * 3072;      // per-b stride inside qkv
    const long long sq_lo = 128LL;               // per-head stride inside qkv
    const long long ss_hi = 8LL * 1024 * 1024;   // per-b stride in scores/qer
    const long long ss_lo = 1024LL * 1024;       // per-head stride

    // 0) round weights/Er to tf32 once (numerics match prior rounds)
    roundcopy4<<<3072, 256>>>((const float4*)W_qkv,  (float4*)wq, 786432);
    roundcopy4<<<1024, 256>>>((const float4*)W_o,    (float4*)wo, 262144);
    roundcopy4<<<4096, 256>>>((const float4*)W_fc,   (float4*)wf, 1048576);
    roundcopy4<<<4096, 256>>>((const float4*)W_proj, (float4*)wp, 1048576);
    roundcopy4<<<128, 256>>>((const float4*)Er,      (float4*)er, 32768);

    // 1) LN1 (rounded)
    ln_kernel<<<8192, 256>>>(x, ln1_g, ln1_b, ln);

    // 2) QKV = ln @ W_qkv + b_qkv   (8192 x 3072 x 1024), rounded out
    gemm_tf32<false><<<dim3(24, 64, 1), 256>>>(
        ln, 1024, 0, 0, wq, 3072, 0, 0, qkv, 3072, 0, 0,
        3072, 1024, b_qkv, nullptr, 1, 0, 1);

    // 3) QEr[bh] = q @ Er^T   (batched 64, anti-tri skip)
    gemm_tf32<true><<<dim3(8, 8, 64), 256>>>(
        qkv, 3072, sq_hi, sq_lo, er, 128, 0, 0, qer, 1024, ss_hi, ss_lo,
        1024, 128, nullptr, nullptr, 0, 2, 0);

    // 4) S[bh] = q @ k^T      (batched 64, lower-tri only)
    gemm_tf32<true><<<dim3(8, 8, 64), 256>>>(
        qkv, 3072, sq_hi, sq_lo, qkv + 1024, 3072, sq_hi, sq_lo, sc, 1024, ss_hi, ss_lo,
        1024, 128, nullptr, nullptr, 0, 1, 0);

    // 5) P = causal softmax((S + skew(QEr)) / sqrt(hs)), rounded, in-place
    softmax_kernel<<<dim3(1024, 64), 256>>>(sc, qer, sc);

    // 6) y[bh] = P @ v        (batched 64, causal K bound), rounded out
    gemm_tf32<false><<<dim3(1, 8, 64), 256>>>(
        sc, 1024, ss_hi, ss_lo, qkv + 2048, 3072, sq_hi, sq_lo,
        yb, 1024, 1024LL * 1024, 128,
        128, 1024, nullptr, nullptr, 0, 3, 1);

    // 7) x1 = x + y @ W_o + b_o  (8192 x 1024 x 1024) -> d_out (fp32)
    gemm_tf32<false><<<dim3(8, 64, 1), 256>>>(
        yb, 1024, 0, 0, wo, 1024, 0, 0, out, 1024, 0, 0,
        1024, 1024, b_o, x, 3, 0, 0);

    // 8) LN2 (rounded)
    ln_kernel<<<8192, 256>>>(out, ln2_g, ln2_b, ln);

    // 9) h = gelu(ln @ W_fc + b_fc)  (8192 x 4096 x 1024), rounded out
    gemm_tf32<false><<<dim3(32, 64, 1), 256>>>(
        ln, 1024, 0, 0, wf, 4096, 0, 0, hb, 4096, 0, 0,
        4096, 1024, b_fc, nullptr, 2, 0, 1);

    // 10) out = x1 + h @ W_proj + b_proj  (8192 x 1024 x 4096) (fp32)
    gemm_tf32<false><<<dim3(8, 64, 1), 256>>>(
        hb, 4096, 0, 0, wp, 1024, 0, 0, out, 1024, 0, 0,
        1024, 4096, b_proj, out, 3, 0, 0);
}

// round 7
// speedup vs baseline: 2.6492x; 1.5270x over previous
#include <cuda_runtime.h>
#include <cuda_fp16.h>
#include <math.h>
#include <stdint.h>

// Problem constants: B=8, L=1024, D=1024, F=4096, nh=8, hs=128, M=B*L=8192

// fp32 scratch
__device__ float g_scores[67108864];   // 64*1024*1024  S (fp32)
__device__ float g_qer[67108864];      // 64*1024*1024  QEr (fp32)
// fp16 scratch
__device__ __half g_ln[8388608];       // LN output
__device__ __half g_qkv[25165824];     // QKV
__device__ __half g_p[67108864];       // softmax P
__device__ __half g_y[8388608];        // attn out
__device__ __half g_hh[33554432];      // MLP hidden
__device__ __half g_wq[3145728];       // W_qkv^T  (3072 x 1024)
__device__ __half g_wo[1048576];       // W_o^T    (1024 x 1024)
__device__ __half g_wf[4194304];       // W_fc^T   (4096 x 1024)
__device__ __half g_wp[4194304];       // W_proj^T (1024 x 4096)
__device__ __half g_vt[8388608];       // v^T per head (64 x 128 x 1024)
__device__ __half g_er[131072];        // Er (1024 x 128)

__device__ __forceinline__ uint32_t smem_u32(const void* p) {
    uint32_t a;
    asm("{ .reg .u64 t; cvta.to.shared.u64 t, %1; cvt.u32.u64 %0, t; }" : "=r"(a) : "l"(p));
    return a;
}
__device__ __forceinline__ void cpa16(uint32_t dst, const void* src) {
    asm volatile("cp.async.cg.shared.global [%0], [%1], 16;\n" :: "r"(dst), "l"(src));
}
#define CPA_COMMIT() asm volatile("cp.async.commit_group;\n" ::: "memory")
#define CPA_WAIT1()  asm volatile("cp.async.wait_group 1;\n" ::: "memory")

__device__ __forceinline__ void ldsm4(uint32_t& r0, uint32_t& r1, uint32_t& r2, uint32_t& r3,
                                      uint32_t addr) {
    asm volatile("ldmatrix.sync.aligned.m8n8.x4.shared.b16 {%0,%1,%2,%3}, [%4];"
                 : "=r"(r0), "=r"(r1), "=r"(r2), "=r"(r3) : "r"(addr));
}
__device__ __forceinline__ void mma_f16(float c[4], const uint32_t a[4],
                                        uint32_t b0, uint32_t b1) {
    asm volatile(
        "mma.sync.aligned.m16n8k16.row.col.f32.f16.f16.f32 "
        "{%0,%1,%2,%3}, {%4,%5,%6,%7}, {%8,%9}, {%0,%1,%2,%3};"
        : "+f"(c[0]), "+f"(c[1]), "+f"(c[2]), "+f"(c[3])
        : "r"(a[0]), "r"(a[1]), "r"(a[2]), "r"(a[3]), "r"(b0), "r"(b1));
}

// ---------------------------------------------------------------------------
// fp16 mma.sync GEMM: C[MxN] = A[MxK] * Bt[NxK]^T, A/Bt fp16 K-major.
// Block tile 128x128, k-step 32, 3-stage cp.async, 8 warps (2m x 4n).
// smem per stage: A 128 rows x 80B (64B data + 16B pad) + B same = 20480B.
// Batched via blockIdx.z: hi=z>>3, lo=z&7.
// epilogue: 0=none, 1=+bias, 2=+bias+GELU, 3=+bias+residual(fp32)
// tri: 0=full, 1=lower-tri skip, 2=anti-tri skip, 3=causal K bound
// half_out: 1 -> C is __half, else float
// ---------------------------------------------------------------------------
__global__ void __launch_bounds__(256, 2)
gemm_f16(const __half* __restrict__ A, int lda, long long sAhi, long long sAlo,
         const __half* __restrict__ Bt, int ldb, long long sBhi, long long sBlo,
         void* __restrict__ Cv, int ldc, long long sChi, long long sClo,
         int N, int K,
         const float* __restrict__ bias, const float* __restrict__ resid,
         int epilogue, int tri, int half_out)
{
    const int n0 = blockIdx.x * 128;
    const int m0 = blockIdx.y * 128;
    if (tri == 1 && n0 > m0) return;
    if (tri == 2 && (m0 + n0) < (N - 255)) return;
    const int kmax = (tri == 3) ? min(K, m0 + 128) : K;
    const int ns = kmax >> 5;   // k-tiles of 32

    const int z = blockIdx.z, hi = z >> 3, lo = z & 7;
    A  += hi * sAhi + lo * sAlo;
    Bt += hi * sBhi + lo * sBlo;
    const long long coff = hi * sChi + lo * sClo;

    extern __shared__ __align__(16) char smem[];
    const uint32_t sbase = smem_u32(smem);

    const int tid  = threadIdx.x;
    const int lane = tid & 31;
    const int warp = tid >> 5;
    const int g  = lane >> 2;
    const int tg = lane & 3;
    const int wm = (warp >> 2) * 64;
    const int wn = (warp & 3) * 32;

    // staging: row = tid>>1 (0..127), chunks c0=(tid&1)*2, c0+1  (16B chunks of 8 halves)
    const int srow = tid >> 1;
    const int c0   = (tid & 1) * 2;
    const uint32_t dA = (uint32_t)(srow * 80 + c0 * 16);
    const __half* Ap = A + (size_t)(m0 + srow) * lda + c0 * 8;
    const __half* Bp = Bt + (size_t)(n0 + srow) * ldb + c0 * 8;

    // ldmatrix lane addresses (lane&15 -> row within 16, lane>>4 -> k chunk 0/1)
    const uint32_t lmA = sbase +         (uint32_t)((wm + (lane & 15)) * 80 + (lane >> 4) * 16);
    const uint32_t lmB = sbase + 10240 + (uint32_t)((wn + (lane & 15)) * 80 + (lane >> 4) * 16);

#define STAGE(s_, p_) do { \
        const uint32_t db_ = sbase + (uint32_t)(p_) * 20480u; \
        const __half* ga_ = Ap + ((s_) << 5); \
        const __half* gb_ = Bp + ((s_) << 5); \
        cpa16(db_ + dA, ga_); \
        cpa16(db_ + dA + 16, ga_ + 8); \
        cpa16(db_ + 10240 + dA, gb_); \
        cpa16(db_ + 10240 + dA + 16, gb_ + 8); \
    } while (0)

    float acc[4][4][4] = {};

    STAGE(0, 0); CPA_COMMIT();
    STAGE(1, 1); CPA_COMMIT();

    int p = 0;
    for (int s = 0; s < ns; s++) {
        CPA_WAIT1();
        __syncthreads();
        const uint32_t pb = (uint32_t)p * 20480u;
#pragma unroll
        for (int k16 = 0; k16 < 2; k16++) {
            uint32_t af[4][4], bf[4][2];
#pragma unroll
            for (int mt = 0; mt < 4; mt++)
                ldsm4(af[mt][0], af[mt][1], af[mt][2], af[mt][3],
                      lmA + pb + mt * 1280u + k16 * 32u);
#pragma unroll
            for (int ntp = 0; ntp < 2; ntp++)
                ldsm4(bf[ntp * 2][0], bf[ntp * 2 + 1][0], bf[ntp * 2][1], bf[ntp * 2 + 1][1],
                      lmB + pb + ntp * 1280u + k16 * 32u);
#pragma unroll
            for (int mt = 0; mt < 4; mt++)
#pragma unroll
                for (int nt = 0; nt < 4; nt++)
                    mma_f16(acc[mt][nt], af[mt], bf[nt][0], bf[nt][1]);
        }
        if (s + 2 < ns) {
            const int p2 = (p + 2 >= 3) ? (p + 2 - 3) : (p + 2);
            STAGE(s + 2, p2);
        }
        CPA_COMMIT();
        p = (p + 1 == 3) ? 0 : (p + 1);
    }

    // Epilogue: acc[mt][nt] -> rows (r, r+8), cols (cb, cb+1)
#pragma unroll
    for (int mt = 0; mt < 4; mt++) {
#pragma unroll
        for (int nt = 0; nt < 4; nt++) {
            const int r  = m0 + wm + mt * 16 + g;
            const int cb = n0 + wn + nt * 8 + tg * 2;
            float b0 = 0.f, b1 = 0.f;
            if (epilogue) { b0 = bias[cb]; b1 = bias[cb + 1]; }
            float o00 = acc[mt][nt][0] + b0, o01 = acc[mt][nt][1] + b1;
            float o10 = acc[mt][nt][2] + b0, o11 = acc[mt][nt][3] + b1;
            const size_t i0 = (size_t)coff + (size_t)r * ldc + cb;
            const size_t i1 = (size_t)coff + (size_t)(r + 8) * ldc + cb;
            if (epilogue == 2) {
                o00 *= normcdff(o00); o01 *= normcdff(o01);
                o10 *= normcdff(o10); o11 *= normcdff(o11);
            } else if (epilogue == 3) {
                const float2 r0 = *(const float2*)(resid + i0);
                const float2 r1 = *(const float2*)(resid + i1);
                o00 += r0.x; o01 += r0.y; o10 += r1.x; o11 += r1.y;
            }
            if (half_out) {
                *(__half2*)((__half*)Cv + i0) = __floats2half2_rn(o00, o01);
                *(__half2*)((__half*)Cv + i1) = __floats2half2_rn(o10, o11);
            } else {
                *(float2*)((float*)Cv + i0) = make_float2(o00, o01);
                *(float2*)((float*)Cv + i1) = make_float2(o10, o11);
            }
        }
    }
#undef STAGE
}

// ---------------------------------------------------------------------------
// Transpose fp32 -> fp16: out[c][r] = (half)in[r][c]
// ---------------------------------------------------------------------------
__global__ void __launch_bounds__(256)
transpose_f2h(const float* __restrict__ in, int ldi,
              __half* __restrict__ out, int ldo)
{
    __shared__ float t[32][33];
    const int c = blockIdx.x * 32 + threadIdx.x;
    const int r = blockIdx.y * 32 + threadIdx.y;
#pragma unroll
    for (int i = 0; i < 32; i += 8)
        t[threadIdx.y + i][threadIdx.x] = in[(size_t)(r + i) * ldi + c];
    __syncthreads();
    const int co = blockIdx.y * 32 + threadIdx.x;
    const int ro = blockIdx.x * 32 + threadIdx.y;
#pragma unroll
    for (int i = 0; i < 32; i += 8)
        out[(size_t)(ro + i) * ldo + co] = __float2half_rn(t[threadIdx.x][threadIdx.y + i]);
}

// Transpose fp16 -> fp16 with batch strides (for vT)
__global__ void __launch_bounds__(256)
transpose_h2h(const __half* __restrict__ in, long long sIhi, long long sIlo, int ldi,
              __half* __restrict__ out, long long sOhi, long long sOlo, int ldo)
{
    __shared__ __half t[32][34];
    const int z = blockIdx.z, hi = z >> 3, lo = z & 7;
    in  += hi * sIhi + lo * sIlo;
    out += hi * sOhi + lo * sOlo;
    const int c = blockIdx.x * 32 + threadIdx.x;
    const int r = blockIdx.y * 32 + threadIdx.y;
#pragma unroll
    for (int i = 0; i < 32; i += 8)
        t[threadIdx.y + i][threadIdx.x] = in[(size_t)(r + i) * ldi + c];
    __syncthreads();
    const int co = blockIdx.y * 32 + threadIdx.x;
    const int ro = blockIdx.x * 32 + threadIdx.y;
#pragma unroll
    for (int i = 0; i < 32; i += 8)
        out[(size_t)(ro + i) * ldo + co] = t[threadIdx.x][threadIdx.y + i];
}

__global__ void __launch_bounds__(256)
copy_f2h(const float4* __restrict__ in, __half* __restrict__ out, int n4)
{
    const int i = blockIdx.x * 256 + threadIdx.x;
    if (i < n4) {
        const float4 v = in[i];
        *(__half2*)(out + i * 4)     = __floats2half2_rn(v.x, v.y);
        *(__half2*)(out + i * 4 + 2) = __floats2half2_rn(v.z, v.w);
    }
}

// ---------------------------------------------------------------------------
// LayerNorm (rows of 1024), fp32 in -> fp16 out.
// ---------------------------------------------------------------------------
__global__ void __launch_bounds__(256)
ln_kernel(const float* __restrict__ x, const float* __restrict__ g,
          const float* __restrict__ b, __half* __restrict__ out)
{
    const int row = blockIdx.x;
    const int tid = threadIdx.x;
    const float4 xv = ((const float4*)(x + (size_t)row * 1024))[tid];

    float s  = xv.x + xv.y + xv.z + xv.w;
    float ss = xv.x * xv.x + xv.y * xv.y + xv.z * xv.z + xv.w * xv.w;
#pragma unroll
    for (int o = 16; o; o >>= 1) {
        s  += __shfl_xor_sync(0xffffffffu, s, o);
        ss += __shfl_xor_sync(0xffffffffu, ss, o);
    }
    __shared__ float sm[16];
    if ((tid & 31) == 0) { sm[tid >> 5] = s; sm[8 + (tid >> 5)] = ss; }
    __syncthreads();
    float S = 0.f, SS = 0.f;
#pragma unroll
    for (int i = 0; i < 8; i++) { S += sm[i]; SS += sm[8 + i]; }
    const float mu  = S * (1.f / 1024.f);
    const float var = SS * (1.f / 1024.f) - mu * mu;
    const float rs  = rsqrtf(var + 1e-5f);

    const float4 gv = ((const float4*)g)[tid];
    const float4 bv = ((const float4*)b)[tid];
    __half* orow = out + (size_t)row * 1024 + tid * 4;
    *(__half2*)(orow)     = __floats2half2_rn((xv.x - mu) * rs * gv.x + bv.x,
                                              (xv.y - mu) * rs * gv.y + bv.y);
    *(__half2*)(orow + 2) = __floats2half2_rn((xv.z - mu) * rs * gv.z + bv.z,
                                              (xv.w - mu) * rs * gv.w + bv.w);
}

// ---------------------------------------------------------------------------
// Causal softmax with skewed relative bias: S,E fp32 in -> P fp16 out.
// ---------------------------------------------------------------------------
__global__ void __launch_bounds__(256)
softmax_kernel(const float* __restrict__ S, const float* __restrict__ E,
               __half* __restrict__ P)
{
    const int q  = blockIdx.x;
    const int bh = blockIdx.y;
    const size_t base = ((size_t)bh * 1024 + q) * 1024;
    const int tid = threadIdx.x;
    const float scale = 0.08838834764831845f;  // 1/sqrt(128)

    float v[4];
    float mx = -3.4e38f;
#pragma unroll
    for (int i = 0; i < 4; i++) {
        const int k = tid + i * 256;
        float val = -3.4e38f;
        if (k <= q) val = (S[base + k] + E[base + k - q + 1023]) * scale;
        v[i] = val;
        mx = fmaxf(mx, val);
    }
#pragma unroll
    for (int o = 16; o; o >>= 1) mx = fmaxf(mx, __shfl_xor_sync(0xffffffffu, mx, o));
    __shared__ float red[8];
    if ((tid & 31) == 0) red[tid >> 5] = mx;
    __syncthreads();
    float m2 = red[0];
#pragma unroll
    for (int i = 1; i < 8; i++) m2 = fmaxf(m2, red[i]);
    __syncthreads();

    float sum = 0.f;
#pragma unroll
    for (int i = 0; i < 4; i++) {
        const float e = (v[i] > -1e37f) ? expf(v[i] - m2) : 0.f;
        v[i] = e;
        sum += e;
    }
#pragma unroll
    for (int o = 16; o; o >>= 1) sum += __shfl_xor_sync(0xffffffffu, sum, o);
    if ((tid & 31) == 0) red[tid >> 5] = sum;
    __syncthreads();
    float tot = 0.f;
#pragma unroll
    for (int i = 0; i < 8; i++) tot += red[i];
    const float inv = 1.f / tot;
#pragma unroll
    for (int i = 0; i < 4; i++) {
        const int k = tid + i * 256;
        P[base + k] = __float2half_rn(v[i] * inv);
    }
}

// ---------------------------------------------------------------------------
extern "C" void kernel_launch(void* const* d_in, const int* in_sizes, int n_in,
                              void* d_out, int out_size)
{
    (void)in_sizes; (void)n_in; (void)out_size;
    const float* x      = (const float*)d_in[0];
    const float* W_qkv  = (const float*)d_in[1];
    const float* b_qkv  = (const float*)d_in[2];
    const float* W_o    = (const float*)d_in[3];
    const float* b_o    = (const float*)d_in[4];
    const float* Er     = (const float*)d_in[5];
    const float* ln1_g  = (const float*)d_in[6];
    const float* ln1_b  = (const float*)d_in[7];
    const float* ln2_g  = (const float*)d_in[8];
    const float* ln2_b  = (const float*)d_in[9];
    const float* W_fc   = (const float*)d_in[10];
    const float* b_fc   = (const float*)d_in[11];
    const float* W_proj = (const float*)d_in[12];
    const float* b_proj = (const float*)d_in[13];
    float* out = (float*)d_out;

    float *sc, *qer;
    __half *ln, *qkv, *pb, *yb, *hb, *wq, *wo, *wf, *wp, *vt, *er;
    cudaGetSymbolAddress((void**)&sc,  g_scores);
    cudaGetSymbolAddress((void**)&qer, g_qer);
    cudaGetSymbolAddress((void**)&ln,  g_ln);
    cudaGetSymbolAddress((void**)&qkv, g_qkv);
    cudaGetSymbolAddress((void**)&pb,  g_p);
    cudaGetSymbolAddress((void**)&yb,  g_y);
    cudaGetSymbolAddress((void**)&hb,  g_hh);
    cudaGetSymbolAddress((void**)&wq,  g_wq);
    cudaGetSymbolAddress((void**)&wo,  g_wo);
    cudaGetSymbolAddress((void**)&wf,  g_wf);
    cudaGetSymbolAddress((void**)&wp,  g_wp);
    cudaGetSymbolAddress((void**)&vt,  g_vt);
    cudaGetSymbolAddress((void**)&er,  g_er);

    const int SMEM_DYN = 61440;   // 3 stages x 20480
    cudaFuncSetAttribute(gemm_f16, cudaFuncAttributeMaxDynamicSharedMemorySize, SMEM_DYN);

    const long long sq_hi = 1024LL * 3072;      // per-b stride in qkv (halves)
    const long long sq_lo = 128LL;               // per-head stride in qkv
    const long long ss_hi = 8LL * 1024 * 1024;   // per-b stride in scores/qer/P
    const long long ss_lo = 1024LL * 1024;       // per-head stride
    const long long sv_hi = 8LL * 131072;        // per-b stride in vT
    const long long sv_lo = 131072LL;            // per-head stride in vT

    // 0) one-time weight transposes (fp32 -> fp16, N x K) and Er copy
    transpose_f2h<<<dim3(96, 32),  dim3(32, 8)>>>(W_qkv,  3072, wq, 1024);
    transpose_f2h<<<dim3(32, 32),  dim3(32, 8)>>>(W_o,    1024, wo, 1024);
    transpose_f2h<<<dim3(128, 32), dim3(32, 8)>>>(W_fc,   4096, wf, 1024);
    transpose_f2h<<<dim3(32, 128), dim3(32, 8)>>>(W_proj, 1024, wp, 4096);
    copy_f2h<<<128, 256>>>((const float4*)Er, er, 32768);

    // 1) LN1 -> fp16
    ln_kernel<<<8192, 256>>>(x, ln1_g, ln1_b, ln);

    // 2) QKV = ln @ W_qkv + b_qkv  (8192 x 3072 x 1024) -> fp16
    gemm_f16<<<dim3(24, 64, 1), 256, SMEM_DYN>>>(
        ln, 1024, 0, 0, wq, 1024, 0, 0, qkv, 3072, 0, 0,
        3072, 1024, b_qkv, nullptr, 1, 0, 1);

    // 2b) vT[bh] = v^T (128 x 1024 per head), fp16
    transpose_h2h<<<dim3(4, 32, 64), dim3(32, 8)>>>(
        qkv + 2048, sq_hi, sq_lo, 3072, vt, sv_hi, sv_lo, 1024);

    // 3) QEr[bh] = q @ Er^T  (batched 64, anti-tri skip) -> fp32
    gemm_f16<<<dim3(8, 8, 64), 256, SMEM_DYN>>>(
        qkv, 3072, sq_hi, sq_lo, er, 128, 0, 0, qer, 1024, ss_hi, ss_lo,
        1024, 128, nullptr, nullptr, 0, 2, 0);

    // 4) S[bh] = q @ k^T  (batched 64, lower-tri only) -> fp32
    gemm_f16<<<dim3(8, 8, 64), 256, SMEM_DYN>>>(
        qkv, 3072, sq_hi, sq_lo, qkv + 1024, 3072, sq_hi, sq_lo, sc, 1024, ss_hi, ss_lo,
        1024, 128, nullptr, nullptr, 0, 1, 0);

    // 5) P = causal softmax((S + skew(QEr)) / sqrt(hs)) -> fp16
    softmax_kernel<<<dim3(1024, 64), 256>>>(sc, qer, pb);

    // 6) y[bh] = P @ v  (batched 64, causal K bound) -> fp16
    gemm_f16<<<dim3(1, 8, 64), 256, SMEM_DYN>>>(
        pb, 1024, ss_hi, ss_lo, vt, 1024, sv_hi, sv_lo,
        yb, 1024, 1024LL * 1024, 128,
        128, 1024, nullptr, nullptr, 0, 3, 1);

    // 7) x1 = x + y @ W_o + b_o  (8192 x 1024 x 1024) -> d_out fp32
    gemm_f16<<<dim3(8, 64, 1), 256, SMEM_DYN>>>(
        yb, 1024, 0, 0, wo, 1024, 0, 0, out, 1024, 0, 0,
        1024, 1024, b_o, x, 3, 0, 0);

    // 8) LN2 -> fp16
    ln_kernel<<<8192, 256>>>(out, ln2_g, ln2_b, ln);

    // 9) h = gelu(ln @ W_fc + b_fc)  (8192 x 4096 x 1024) -> fp16
    gemm_f16<<<dim3(32, 64, 1), 256, SMEM_DYN>>>(
        ln, 1024, 0, 0, wf, 1024, 0, 0, hb, 4096, 0, 0,
        4096, 1024, b_fc, nullptr, 2, 0, 1);

    // 10) out = x1 + h @ W_proj + b_proj  (8192 x 1024 x 4096) -> fp32
    gemm_f16<<<dim3(8, 64, 1), 256, SMEM_DYN>>>(
        hb, 4096, 0, 0, wp, 4096, 0, 0, out, 1024, 0, 0,
        1024, 4096, b_proj, out, 3, 0, 0);
}